// round 6
// baseline (speedup 1.0000x reference)
#include <cuda_runtime.h>
#include <cuda_bf16.h>
#include <cstdint>
#include <cmath>

#define NROWS 8192
#define XROWS 16384
#define DIM   64
#define BT    128                 // tile dim
#define NT    (XROWS / BT)        // 128 tiles per side
#define LPAD  72                  // padded smem row stride (bf16): conflict-free ldmatrix
#define TCHUNK 4                  // row-tiles per job (strip length)
#define NJOBS 2112                // sum_{bj=0}^{127} ceil((bj+1)/4)

#define SCALE_L2E 28.853900817779268f   // 20 * log2(e)

// ---------------- device scratch ----------------
__device__ __align__(16) __nv_bfloat16 g_Xs[XROWS * DIM];  // normalized * 20*log2(e)
__device__ __align__(16) __nv_bfloat16 g_Xn[XROWS * DIM];  // normalized
__device__ float g_part[XROWS];
__device__ float g_pos[NROWS];

static __device__ __forceinline__ uint32_t smem_u32(const void* p) {
    uint32_t a;
    asm("{ .reg .u64 t; cvta.to.shared.u64 t, %1; cvt.u32.u64 %0, t; }" : "=r"(a) : "l"(p));
    return a;
}
static __device__ __forceinline__ float ex2f(float x) {
    float y; asm("ex2.approx.ftz.f32 %0, %1;" : "=f"(y) : "f"(x)); return y;
}
// jobs before column bj:  F(bj) = 2q(q+1) + r(q+1),  bj = 4q + r
static __device__ __forceinline__ int jobs_before(int bj) {
    int q = bj >> 2, r = bj & 3;
    return 2 * q * (q + 1) + r * (q + 1);
}

// ---------------- kernel 1: fused normalize + bf16 + exact pos logit + zeroing ----------------
__global__ void prep_kernel(const float* __restrict__ A, const float* __restrict__ P,
                            float* __restrict__ out) {
    int row  = blockIdx.x * 8 + (threadIdx.x >> 5);
    int lane = threadIdx.x & 31;
    float a0 = A[(size_t)row * DIM + lane], a1 = A[(size_t)row * DIM + lane + 32];
    float p0 = P[(size_t)row * DIM + lane], p1 = P[(size_t)row * DIM + lane + 32];
    float sa = a0 * a0 + a1 * a1;
    float sp = p0 * p0 + p1 * p1;
    float d  = a0 * p0 + a1 * p1;
    #pragma unroll
    for (int o = 16; o; o >>= 1) {
        sa += __shfl_xor_sync(0xffffffffu, sa, o);
        sp += __shfl_xor_sync(0xffffffffu, sp, o);
        d  += __shfl_xor_sync(0xffffffffu, d,  o);
    }
    float ra = rsqrtf(fmaxf(sa, 1e-24f));
    float rp = rsqrtf(fmaxf(sp, 1e-24f));
    float va0 = a0 * ra, va1 = a1 * ra;
    float vp0 = p0 * rp, vp1 = p1 * rp;
    size_t ia = (size_t)row * DIM, ip = (size_t)(row + NROWS) * DIM;
    g_Xn[ia + lane]      = __float2bfloat16(va0);
    g_Xn[ia + lane + 32] = __float2bfloat16(va1);
    g_Xn[ip + lane]      = __float2bfloat16(vp0);
    g_Xn[ip + lane + 32] = __float2bfloat16(vp1);
    g_Xs[ia + lane]      = __float2bfloat16(va0 * SCALE_L2E);
    g_Xs[ia + lane + 32] = __float2bfloat16(va1 * SCALE_L2E);
    g_Xs[ip + lane]      = __float2bfloat16(vp0 * SCALE_L2E);
    g_Xs[ip + lane + 32] = __float2bfloat16(vp1 * SCALE_L2E);
    if (lane == 0) {
        g_pos[row] = 20.0f * d / fmaxf(sqrtf(sa) * sqrtf(sp), 1e-6f);
        g_part[row] = 0.0f;
        g_part[row + NROWS] = 0.0f;
    }
    if (blockIdx.x == 0 && threadIdx.x == 0) out[0] = 0.0f;
}

// ---------------- kernel 2: upper-triangle strip GEMM + exp + row/col sums ----------------
// Job = (bj, chunk of up to 4 bi-tiles, bi<=bj). Row sums flushed per tile;
// column partials live in registers across the strip, reduced once per job.
// Each exp term credits part[row] and part[col] (symmetry). Diagonal tiles keep
// strict upper triangle only (also removes global diagonal == -2*e^{1/T}).
__global__ void __launch_bounds__(256, 2) mma_kernel() {
    __shared__ __nv_bfloat16 Ls[BT][LPAD];
    __shared__ __nv_bfloat16 Rs[BT][LPAD];
    __shared__ float colsum[BT];

    // ---- decode job (big strips first) ----
    int t = NJOBS - 1 - (int)blockIdx.x;
    int bj = (int)sqrtf(8.0f * (float)t) ;
    if (bj > NT - 1) bj = NT - 1;
    while (jobs_before(bj) > t) --bj;
    while (bj < NT - 1 && jobs_before(bj + 1) <= t) ++bj;
    int chunk = t - jobs_before(bj);
    int bi0 = chunk * TCHUNK;
    int bi1 = min(bi0 + TCHUNK - 1, bj);

    int tid = threadIdx.x, wid = tid >> 5, lane = tid & 31;
    int gid = lane >> 2, tig = lane & 3;

    // ---- load Rs once per job; zero colsum ----
    const uint4* Rg = (const uint4*)(g_Xn + (size_t)bj * BT * DIM);
    #pragma unroll
    for (int it = 0; it < 4; ++it) {
        int f = tid + it * 256;
        *(uint4*)&Rs[f >> 3][(f & 7) * 8] = Rg[f];
    }
    if (tid < BT) colsum[tid] = 0.0f;

    int gcol0 = bj * BT;
    int b_u = (lane >> 4) & 1;
    int b_h = (lane >> 3) & 1;
    int b_r = lane & 7;

    float cs[TCHUNK * 2][2][2];   // reuse index: [n2][u][parity] col partials (32 regs)
    #pragma unroll
    for (int i = 0; i < 8; ++i) { cs[i][0][0]=0.f; cs[i][0][1]=0.f; cs[i][1][0]=0.f; cs[i][1][1]=0.f; }

    for (int bi = bi0; bi <= bi1; ++bi) {
        __syncthreads();           // Ls reuse safety (and first-iter Rs/colsum visibility)
        const uint4* Lg = (const uint4*)(g_Xs + (size_t)bi * BT * DIM);
        #pragma unroll
        for (int it = 0; it < 4; ++it) {
            int f = tid + it * 256;
            *(uint4*)&Ls[f >> 3][(f & 7) * 8] = Lg[f];
        }
        __syncthreads();

        bool diag = (bi == bj);
        int grow0 = bi * BT;

        uint32_t a[4][4];
        {
            int r  = wid * 16 + (lane & 15);
            int kh = (lane >> 4) * 8;
            #pragma unroll
            for (int kc = 0; kc < 4; ++kc) {
                uint32_t addr = smem_u32(&Ls[r][kc * 16 + kh]);
                asm volatile("ldmatrix.sync.aligned.m8n8.x4.shared.b16 {%0,%1,%2,%3}, [%4];"
                             : "=r"(a[kc][0]), "=r"(a[kc][1]), "=r"(a[kc][2]), "=r"(a[kc][3])
                             : "r"(addr));
            }
        }

        int myrow0 = grow0 + wid * 16 + gid;
        int myrow1 = myrow0 + 8;
        float row0s = 0.0f, row1s = 0.0f;

        #pragma unroll
        for (int n2 = 0; n2 < 8; ++n2) {
            uint32_t b[2][4][2];
            #pragma unroll
            for (int kc = 0; kc < 4; ++kc) {
                uint32_t addr = smem_u32(&Rs[n2 * 16 + b_u * 8 + b_r][kc * 16 + b_h * 8]);
                asm volatile("ldmatrix.sync.aligned.m8n8.x4.shared.b16 {%0,%1,%2,%3}, [%4];"
                             : "=r"(b[0][kc][0]), "=r"(b[0][kc][1]),
                               "=r"(b[1][kc][0]), "=r"(b[1][kc][1])
                             : "r"(addr));
            }
            float c[2][4] = {};
            #pragma unroll
            for (int kc = 0; kc < 4; ++kc) {
                #pragma unroll
                for (int u = 0; u < 2; ++u) {
                    asm volatile(
                        "mma.sync.aligned.m16n8k16.row.col.f32.bf16.bf16.f32 "
                        "{%0,%1,%2,%3}, {%4,%5,%6,%7}, {%8,%9}, {%0,%1,%2,%3};"
                        : "+f"(c[u][0]), "+f"(c[u][1]), "+f"(c[u][2]), "+f"(c[u][3])
                        : "r"(a[kc][0]), "r"(a[kc][1]), "r"(a[kc][2]), "r"(a[kc][3]),
                          "r"(b[u][kc][0]), "r"(b[u][kc][1]));
                }
            }
            #pragma unroll
            for (int u = 0; u < 2; ++u) {
                float e0 = ex2f(c[u][0]), e1 = ex2f(c[u][1]);
                float e2 = ex2f(c[u][2]), e3 = ex2f(c[u][3]);
                if (diag) {   // strict upper triangle only
                    int gc0 = gcol0 + (n2 * 2 + u) * 8 + tig * 2;
                    if (gc0     <= myrow0) e0 = 0.0f;
                    if (gc0 + 1 <= myrow0) e1 = 0.0f;
                    if (gc0     <= myrow1) e2 = 0.0f;
                    if (gc0 + 1 <= myrow1) e3 = 0.0f;
                }
                row0s += e0 + e1;
                row1s += e2 + e3;
                cs[n2][u][0] += e0 + e2;
                cs[n2][u][1] += e1 + e3;
            }
        }

        // per-tile row flush: reduce over the 4 tig lanes, then global atomics
        #pragma unroll
        for (int o = 1; o < 4; o <<= 1) {
            row0s += __shfl_xor_sync(0xffffffffu, row0s, o);
            row1s += __shfl_xor_sync(0xffffffffu, row1s, o);
        }
        if (tig == 0) {
            atomicAdd(&g_part[myrow0], row0s);
            atomicAdd(&g_part[myrow1], row1s);
        }
    }

    // ---- per-job column flush: reduce cs over gid lanes (offsets 4,8,16) ----
    #pragma unroll
    for (int n2 = 0; n2 < 8; ++n2) {
        #pragma unroll
        for (int u = 0; u < 2; ++u) {
            #pragma unroll
            for (int p = 0; p < 2; ++p) {
                float v = cs[n2][u][p];
                v += __shfl_xor_sync(0xffffffffu, v, 4);
                v += __shfl_xor_sync(0xffffffffu, v, 8);
                v += __shfl_xor_sync(0xffffffffu, v, 16);
                if (gid == 0)
                    atomicAdd(&colsum[(n2 * 2 + u) * 8 + tig * 2 + p], v);
            }
        }
    }
    __syncthreads();
    if (tid < BT) atomicAdd(&g_part[gcol0 + tid], colsum[tid]);
}

// ---------------- kernel 3: loss reduction straight into d_out ----------------
__global__ void loss_kernel(float* __restrict__ out) {
    __shared__ float wsum[8];
    int i = blockIdx.x * 256 + threadIdx.x;
    float s = __logf(g_part[i] + g_part[i + NROWS]) - g_pos[i];
    #pragma unroll
    for (int o = 16; o; o >>= 1) s += __shfl_xor_sync(0xffffffffu, s, o);
    int wid = threadIdx.x >> 5, lane = threadIdx.x & 31;
    if (lane == 0) wsum[wid] = s;
    __syncthreads();
    if (wid == 0) {
        float v = (lane < 8) ? wsum[lane] : 0.0f;
        #pragma unroll
        for (int o = 4; o; o >>= 1) v += __shfl_xor_sync(0xffffffffu, v, o);
        if (lane == 0) atomicAdd(out, v * (1.0f / (float)NROWS));
    }
}

// ---------------- launch ----------------
extern "C" void kernel_launch(void* const* d_in, const int* in_sizes, int n_in,
                              void* d_out, int out_size) {
    const float* A = (const float*)d_in[0];
    const float* P = (const float*)d_in[1];
    prep_kernel<<<NROWS / 8, 256>>>(A, P, (float*)d_out);
    mma_kernel<<<NJOBS, 256>>>();
    loss_kernel<<<NROWS / 256, 256>>>((float*)d_out);
}